// round 2
// baseline (speedup 1.0000x reference)
#include <cuda_runtime.h>

#define Bb   8
#define Nn   8192
#define Mm   2048
#define Cc   64
#define CTt  64
#define KNN  32

// Scratch (static __device__ allocation is allowed; cudaMalloc is not)
__device__ int   g_idx[Bb * Mm * KNN];            // 2 MB
__device__ float g_featT[(size_t)Bb * Nn * Cc];   // 16 MB  [b][n][c]
__device__ float g_tembT[(size_t)Bb * Nn * CTt];  // 16 MB  [b][n][c]

// ---------------------------------------------------------------------------
// Transpose [B][C][N] -> [B][N][C] for feat and temb (C == CT == 64)
// grid: (N/32, C/32, B*2), block: (32, 8)
// ---------------------------------------------------------------------------
__global__ void transpose_kernel(const float* __restrict__ feat,
                                 const float* __restrict__ temb)
{
    __shared__ float tile[32][33];
    int zz    = blockIdx.z;
    int b     = zz >> 1;
    int which = zz & 1;
    const float* src = which ? temb : feat;
    float*       dst = which ? g_tembT : g_featT;

    int n0 = blockIdx.x * 32;
    int c0 = blockIdx.y * 32;
    int tx = threadIdx.x, ty = threadIdx.y;

    const float* s = src + (size_t)b * Cc * Nn;
    float*       d = dst + (size_t)b * Nn * Cc;

#pragma unroll
    for (int i = 0; i < 32; i += 8)
        tile[ty + i][tx] = s[(size_t)(c0 + ty + i) * Nn + n0 + tx];
    __syncthreads();
#pragma unroll
    for (int i = 0; i < 32; i += 8)
        d[(size_t)(n0 + ty + i) * Cc + c0 + tx] = tile[tx][ty + i];
}

// ---------------------------------------------------------------------------
// Ball query: one warp per center. Ordered first-K-valid scan with early exit.
// Arithmetic replicates XLA reference bit-for-bit:
//   cn/pn : mul-then-add reductions (NO fma contraction)
//   cross : fma chain ascending in d (gemm-style accumulation)
//   d2    : fsub(fadd(cn,pn), fmul(2,cross)) as separate rounded ops
// grid: (B*M/8), block: 256 (8 warps)
// ---------------------------------------------------------------------------
__global__ void ballquery_kernel(const float* __restrict__ pts,   // [B][3][N]
                                 const float* __restrict__ ctr)   // [B][3][M]
{
    __shared__ int sidx[8][KNN];
    int warp = threadIdx.x >> 5;
    int lane = threadIdx.x & 31;
    int gw   = blockIdx.x * 8 + warp;          // global center id
    int b    = gw / Mm;
    int m    = gw - b * Mm;

    const float* px = pts + (size_t)b * 3 * Nn;
    const float* py = px + Nn;
    const float* pz = py + Nn;

    float cx = ctr[(size_t)b * 3 * Mm + m];
    float cy = ctr[(size_t)b * 3 * Mm + Mm + m];
    float cz = ctr[(size_t)b * 3 * Mm + 2 * Mm + m];
    // cn = fl(cx^2) + fl(cy^2) + fl(cz^2), mul-then-add, no contraction
    float cn = __fadd_rn(__fadd_rn(__fmul_rn(cx, cx), __fmul_rn(cy, cy)),
                         __fmul_rn(cz, cz));

    const float R2 = (float)(0.2 * 0.2);

    int count = 0;
    for (int j = lane; j < Nn && count < KNN; j += 32) {
        float x = __ldg(px + j);
        float y = __ldg(py + j);
        float z = __ldg(pz + j);
        // pn: mul-then-add reduction
        float pn = __fadd_rn(__fadd_rn(__fmul_rn(x, x), __fmul_rn(y, y)),
                             __fmul_rn(z, z));
        // cross: gemm-style fma chain, ascending in d
        float cross = fmaf(cz, z, fmaf(cy, y, __fmul_rn(cx, x)));
        // d2 = (cn + pn) - 2*cross, separate rounded ops
        float d2 = __fsub_rn(__fadd_rn(cn, pn), __fmul_rn(2.0f, cross));
        bool valid  = d2 < R2;
        unsigned mask = __ballot_sync(0xffffffffu, valid);
        if (valid) {
            int pos = count + __popc(mask & ((1u << lane) - 1u));
            if (pos < KNN) sidx[warp][pos] = j;
        }
        count += __popc(mask);
    }
    __syncwarp();
    int cnt   = min(count, KNN);
    int first = (cnt > 0) ? sidx[warp][0] : 0;
    int v     = (lane < cnt) ? sidx[warp][lane] : first;
    g_idx[(size_t)gw * KNN + lane] = v;
}

// ---------------------------------------------------------------------------
// Gather + emit. One CTA per center.
// out1 [B][67][M][K] : c<3 -> coord diff, c>=3 -> feat
// out2 [B][64][M][K] : temb
// ---------------------------------------------------------------------------
__global__ void gather_kernel(const float* __restrict__ pts,
                              const float* __restrict__ ctr,
                              float* __restrict__ out1,
                              float* __restrict__ out2)
{
    __shared__ float sf[KNN][65];   // padded pitch 65 -> conflict-free reads
    __shared__ float st[KNN][65];
    __shared__ int   sidx[KNN];
    __shared__ float sc[3];

    int gw = blockIdx.x;
    int b  = gw / Mm;
    int m  = gw - b * Mm;
    int t  = threadIdx.x;

    if (t < KNN) sidx[t] = g_idx[(size_t)gw * KNN + t];
    if (t < 3)   sc[t]   = ctr[(size_t)b * 3 * Mm + t * Mm + m];
    __syncthreads();

    // Stage neighbors: 32 neighbors x 16 float4 per tensor; 256 thr x 2 iters
    const float4* fT = (const float4*)g_featT + (size_t)b * Nn * (Cc / 4);
    const float4* tT = (const float4*)g_tembT + (size_t)b * Nn * (CTt / 4);
#pragma unroll
    for (int it = 0; it < 2; it++) {
        int e  = t + it * 256;          // 0..511
        int k  = e >> 4;
        int c4 = e & 15;
        int n  = sidx[k];
        float4 v = fT[(size_t)n * (Cc / 4) + c4];
        sf[k][c4 * 4 + 0] = v.x; sf[k][c4 * 4 + 1] = v.y;
        sf[k][c4 * 4 + 2] = v.z; sf[k][c4 * 4 + 3] = v.w;
        float4 w = tT[(size_t)n * (CTt / 4) + c4];
        st[k][c4 * 4 + 0] = w.x; st[k][c4 * 4 + 1] = w.y;
        st[k][c4 * 4 + 2] = w.z; st[k][c4 * 4 + 3] = w.w;
    }
    __syncthreads();

    // Emit neighbor_features: 67*32 elements, coalesced along k
    for (int e = t; e < 67 * KNN; e += 256) {
        int c = e >> 5;
        int k = e & 31;
        float v;
        if (c < 3) {
            int n = sidx[k];
            v = __fsub_rn(__ldg(pts + (size_t)b * 3 * Nn + (size_t)c * Nn + n),
                          sc[c]);
        } else {
            v = sf[k][c - 3];
        }
        out1[(((size_t)b * 67 + c) * Mm + m) * KNN + k] = v;
    }
    // Emit temb_grouped: 64*32 elements
    for (int e = t; e < CTt * KNN; e += 256) {
        int c = e >> 5;
        int k = e & 31;
        out2[(((size_t)b * CTt + c) * Mm + m) * KNN + k] = st[k][c];
    }
}

// ---------------------------------------------------------------------------
extern "C" void kernel_launch(void* const* d_in, const int* in_sizes, int n_in,
                              void* d_out, int out_size)
{
    const float* pts  = (const float*)d_in[0];   // points_coords  [B,3,N]
    const float* ctr  = (const float*)d_in[1];   // centers_coords [B,3,M]
    const float* temb = (const float*)d_in[2];   // temb           [B,CT,N]
    const float* feat = (const float*)d_in[3];   // points_features[B,C,N]

    float* out1 = (float*)d_out;                                   // [B,67,M,K]
    float* out2 = out1 + (size_t)Bb * (3 + Cc) * Mm * KNN;         // [B,CT,M,K]

    dim3 tb(32, 8);
    dim3 tg(Nn / 32, Cc / 32, Bb * 2);
    transpose_kernel<<<tg, tb>>>(feat, temb);

    ballquery_kernel<<<(Bb * Mm) / 8, 256>>>(pts, ctr);

    gather_kernel<<<Bb * Mm, 256>>>(pts, ctr, out1, out2);
}

// round 3
// speedup vs baseline: 1.4974x; 1.4974x over previous
#include <cuda_runtime.h>

#define Bb   8
#define Nn   8192
#define Mm   2048
#define Cc   64
#define CTt  64
#define KNN  32

// Scratch (__device__ globals; cudaMalloc is forbidden)
__device__ float  g_featT[(size_t)Bb * Nn * Cc];   // 16 MB  [b][n][c]
__device__ float  g_tembT[(size_t)Bb * Nn * CTt];  // 16 MB  [b][n][c]
__device__ float4 g_xyz[(size_t)Bb * Nn];          //  4 MB  (x,y,z,|p|^2)

// ---------------------------------------------------------------------------
// Prep A: transpose [B][C][N] -> [B][N][C] for feat and temb
// ---------------------------------------------------------------------------
__global__ void transpose_kernel(const float* __restrict__ feat,
                                 const float* __restrict__ temb)
{
    __shared__ float tile[32][33];
    int zz    = blockIdx.z;
    int b     = zz >> 1;
    int which = zz & 1;
    const float* src = which ? temb : feat;
    float*       dst = which ? g_tembT : g_featT;

    int n0 = blockIdx.x * 32;
    int c0 = blockIdx.y * 32;
    int tx = threadIdx.x, ty = threadIdx.y;

    const float* s = src + (size_t)b * Cc * Nn;
    float*       d = dst + (size_t)b * Nn * Cc;

#pragma unroll
    for (int i = 0; i < 32; i += 8)
        tile[ty + i][tx] = s[(size_t)(c0 + ty + i) * Nn + n0 + tx];
    __syncthreads();
#pragma unroll
    for (int i = 0; i < 32; i += 8)
        d[(size_t)(n0 + ty + i) * Cc + c0 + tx] = tile[tx][ty + i];
}

// ---------------------------------------------------------------------------
// Prep B: pack coords + squared norm.  pn uses the exact mul-then-add order
// of the reference (no FMA contraction) so thresholds are bit-identical.
// ---------------------------------------------------------------------------
__global__ void xyz_kernel(const float* __restrict__ pts)   // [B][3][N]
{
    int g = blockIdx.x * blockDim.x + threadIdx.x;          // 0 .. B*N-1
    int b = g >> 13;                                        // /Nn
    int n = g & (Nn - 1);
    const float* p = pts + (size_t)b * 3 * Nn;
    float x = p[n], y = p[Nn + n], z = p[2 * Nn + n];
    float pn = __fadd_rn(__fadd_rn(__fmul_rn(x, x), __fmul_rn(y, y)),
                         __fmul_rn(z, z));
    g_xyz[g] = make_float4(x, y, z, pn);
}

// ---------------------------------------------------------------------------
// Fused ball-query + gather + emit.  One warp per center, 8 warps / CTA.
// Scan processes 128 points per round (4 independent 16B loads per lane).
// After selection, lane k owns neighbor k: it loads that neighbor's full
// channel rows (contiguous float4s) and stores them directly -- the [.,m,k]
// store along k is per-lane, so no transpose / smem staging is needed.
// ---------------------------------------------------------------------------
__global__ void __launch_bounds__(256)
fused_kernel(const float* __restrict__ ctr,    // [B][3][M]
             float* __restrict__ out1,         // [B][67][M][K]
             float* __restrict__ out2)         // [B][64][M][K]
{
    __shared__ int sidx[8][KNN];
    int warp = threadIdx.x >> 5;
    int lane = threadIdx.x & 31;
    int gw   = blockIdx.x * 8 + warp;           // global center id
    int b    = gw >> 11;                        // / Mm
    int m    = gw & (Mm - 1);

    float cx = ctr[(size_t)b * 3 * Mm + m];
    float cy = ctr[(size_t)b * 3 * Mm + Mm + m];
    float cz = ctr[(size_t)b * 3 * Mm + 2 * Mm + m];
    float cn = __fadd_rn(__fadd_rn(__fmul_rn(cx, cx), __fmul_rn(cy, cy)),
                         __fmul_rn(cz, cz));

    const float4* xyz = g_xyz + (size_t)b * Nn;
    const float R2 = (float)(0.2 * 0.2);

    // ---- ordered first-K scan, 128 points per round ----
    int count = 0;
    for (int j0 = 0; j0 < Nn && count < KNN; j0 += 128) {
        float4 p0 = xyz[j0 + lane];
        float4 p1 = xyz[j0 + 32 + lane];
        float4 p2 = xyz[j0 + 64 + lane];
        float4 p3 = xyz[j0 + 96 + lane];
#pragma unroll
        for (int i = 0; i < 4; i++) {
            float4 p = (i == 0) ? p0 : (i == 1) ? p1 : (i == 2) ? p2 : p3;
            float cross = fmaf(cz, p.z, fmaf(cy, p.y, __fmul_rn(cx, p.x)));
            float d2 = __fsub_rn(__fadd_rn(cn, p.w), __fmul_rn(2.0f, cross));
            bool valid = d2 < R2;
            unsigned mask = __ballot_sync(0xffffffffu, valid);
            if (valid) {
                int pos = count + __popc(mask & ((1u << lane) - 1u));
                if (pos < KNN) sidx[warp][pos] = j0 + i * 32 + lane;
            }
            count += __popc(mask);
        }
    }
    __syncwarp();
    int cnt   = min(count, KNN);
    int first = (cnt > 0) ? sidx[warp][0] : 0;
    int n     = (lane < cnt) ? sidx[warp][lane] : first;

    // ---- emit: lane k handles neighbor k entirely ----
    float* o1 = out1 + ((size_t)b * 67 * Mm + m) * KNN + lane;  // channel 0
    float* o2 = out2 + ((size_t)b * 64 * Mm + m) * KNN + lane;
    const size_t cs = (size_t)Mm * KNN;                          // channel stride

    float4 pc = xyz[n];
    o1[0]      = __fsub_rn(pc.x, cx);
    o1[cs]     = __fsub_rn(pc.y, cy);
    o1[2 * cs] = __fsub_rn(pc.z, cz);

    const float4* fT = (const float4*)g_featT + ((size_t)b * Nn + n) * (Cc / 4);
    const float4* tT = (const float4*)g_tembT + ((size_t)b * Nn + n) * (CTt / 4);
    float* o1f = o1 + 3 * cs;
#pragma unroll
    for (int c4 = 0; c4 < Cc / 4; c4++) {
        float4 v = fT[c4];
        o1f[(4 * c4 + 0) * cs] = v.x;
        o1f[(4 * c4 + 1) * cs] = v.y;
        o1f[(4 * c4 + 2) * cs] = v.z;
        o1f[(4 * c4 + 3) * cs] = v.w;
    }
#pragma unroll
    for (int c4 = 0; c4 < CTt / 4; c4++) {
        float4 w = tT[c4];
        o2[(4 * c4 + 0) * cs] = w.x;
        o2[(4 * c4 + 1) * cs] = w.y;
        o2[(4 * c4 + 2) * cs] = w.z;
        o2[(4 * c4 + 3) * cs] = w.w;
    }
}

// ---------------------------------------------------------------------------
extern "C" void kernel_launch(void* const* d_in, const int* in_sizes, int n_in,
                              void* d_out, int out_size)
{
    const float* pts  = (const float*)d_in[0];   // points_coords  [B,3,N]
    const float* ctr  = (const float*)d_in[1];   // centers_coords [B,3,M]
    const float* temb = (const float*)d_in[2];   // temb           [B,CT,N]
    const float* feat = (const float*)d_in[3];   // points_features[B,C,N]

    float* out1 = (float*)d_out;                                   // [B,67,M,K]
    float* out2 = out1 + (size_t)Bb * (3 + Cc) * Mm * KNN;         // [B,64,M,K]

    dim3 tb(32, 8);
    dim3 tg(Nn / 32, Cc / 32, Bb * 2);
    transpose_kernel<<<tg, tb>>>(feat, temb);

    xyz_kernel<<<(Bb * Nn) / 256, 256>>>(pts);

    fused_kernel<<<(Bb * Mm) / 8, 256>>>(ctr, out1, out2);
}

// round 4
// speedup vs baseline: 1.5323x; 1.0234x over previous
#include <cuda_runtime.h>

#define Bb   8
#define Nn   8192
#define Mm   2048
#define Cc   64
#define CTt  64
#define KNN  32
#define TILE 1024

// Scratch (__device__ globals; cudaMalloc is forbidden)
// g_comb row n: [feat c0..63 | temb c0..63]  -> one 512B contiguous gather run
__device__ float  g_comb[(size_t)Bb * Nn * 128];   // 32 MB
__device__ float4 g_xyz[(size_t)Bb * Nn];          //  4 MB  (x,y,z,|p|^2)

// ---------------------------------------------------------------------------
// Prep A: transpose [B][C][N] -> combined [B][N][128] (feat -> cols 0..63,
// temb -> cols 64..127).  Fully float4-vectorized on gmem side.
// block (8,32); grid (Nn/32, Cc/32, B*2)
// ---------------------------------------------------------------------------
__global__ void transpose_kernel(const float* __restrict__ feat,
                                 const float* __restrict__ temb)
{
    __shared__ float tile[32][33];
    int zz    = blockIdx.z;
    int b     = zz >> 1;
    int which = zz & 1;                       // 0: feat, 1: temb
    const float* src = which ? temb : feat;
    int cbase        = which ? 64 : 0;

    int n0 = blockIdx.x * 32;
    int c0 = blockIdx.y * 32;
    int j  = threadIdx.x;                     // 0..7
    int i  = threadIdx.y;                     // 0..31

    const float* s = src + (size_t)b * Cc * Nn;
    float*       d = g_comb + (size_t)b * Nn * 128;

    // load: row c = c0+i, cols n0+4j..+3  (128B per 8 lanes per row)
    float4 v = *(const float4*)(s + (size_t)(c0 + i) * Nn + n0 + 4 * j);
    tile[i][4 * j + 0] = v.x;
    tile[i][4 * j + 1] = v.y;
    tile[i][4 * j + 2] = v.z;
    tile[i][4 * j + 3] = v.w;
    __syncthreads();

    // store: row n = n0+i, cols cbase+c0+4j..+3
    float4 w;
    w.x = tile[4 * j + 0][i];
    w.y = tile[4 * j + 1][i];
    w.z = tile[4 * j + 2][i];
    w.w = tile[4 * j + 3][i];
    *(float4*)(d + (size_t)(n0 + i) * 128 + cbase + c0 + 4 * j) = w;
}

// ---------------------------------------------------------------------------
// Prep B: pack coords + squared norm (exact mul-then-add order).
// ---------------------------------------------------------------------------
__global__ void xyz_kernel(const float* __restrict__ pts)   // [B][3][N]
{
    int g = blockIdx.x * blockDim.x + threadIdx.x;          // 0 .. B*N-1
    int b = g >> 13;
    int n = g & (Nn - 1);
    const float* p = pts + (size_t)b * 3 * Nn;
    float x = p[n], y = p[Nn + n], z = p[2 * Nn + n];
    float pn = __fadd_rn(__fadd_rn(__fmul_rn(x, x), __fmul_rn(y, y)),
                         __fmul_rn(z, z));
    g_xyz[g] = make_float4(x, y, z, pn);
}

// ---------------------------------------------------------------------------
// Fused ball-query + gather + emit.  8 warps/CTA, one center per warp.
// Points staged through a shared 1024-point tile (loaded once per CTA,
// scanned by all 8 warps) -> 8x less L2 scan traffic, LDS-latency scan.
// ---------------------------------------------------------------------------
__global__ void __launch_bounds__(256)
fused_kernel(const float* __restrict__ ctr,    // [B][3][M]
             float* __restrict__ out1,         // [B][67][M][K]
             float* __restrict__ out2)         // [B][64][M][K]
{
    __shared__ float4 spts[TILE];              // 16 KB
    __shared__ int    sidx[8][KNN];

    int t    = threadIdx.x;
    int warp = t >> 5;
    int lane = t & 31;
    int gw   = blockIdx.x * 8 + warp;          // global center id
    int b    = gw >> 11;                       // / Mm
    int m    = gw & (Mm - 1);

    float cx = ctr[(size_t)b * 3 * Mm + m];
    float cy = ctr[(size_t)b * 3 * Mm + Mm + m];
    float cz = ctr[(size_t)b * 3 * Mm + 2 * Mm + m];
    float cn = __fadd_rn(__fadd_rn(__fmul_rn(cx, cx), __fmul_rn(cy, cy)),
                         __fmul_rn(cz, cz));

    const float4* xyz = g_xyz + (size_t)b * Nn;
    const float R2 = (float)(0.2 * 0.2);

    int count = 0;
    for (int t0 = 0; t0 < Nn; t0 += TILE) {
        // cooperative tile load: 256 threads x 4 float4
#pragma unroll
        for (int q = 0; q < 4; q++)
            spts[t + q * 256] = xyz[t0 + t + q * 256];
        __syncthreads();

        if (count < KNN) {
            for (int g = 0; g < TILE && count < KNN; g += 128) {
                float4 p0 = spts[g + lane];
                float4 p1 = spts[g + 32 + lane];
                float4 p2 = spts[g + 64 + lane];
                float4 p3 = spts[g + 96 + lane];
#pragma unroll
                for (int i = 0; i < 4; i++) {
                    float4 p = (i == 0) ? p0 : (i == 1) ? p1
                             : (i == 2) ? p2 : p3;
                    float cross = fmaf(cz, p.z,
                                       fmaf(cy, p.y, __fmul_rn(cx, p.x)));
                    float d2 = __fsub_rn(__fadd_rn(cn, p.w),
                                         __fmul_rn(2.0f, cross));
                    bool valid = d2 < R2;
                    unsigned mask = __ballot_sync(0xffffffffu, valid);
                    if (valid) {
                        int pos = count + __popc(mask & ((1u << lane) - 1u));
                        if (pos < KNN)
                            sidx[warp][pos] = t0 + g + i * 32 + lane;
                    }
                    count += __popc(mask);
                }
            }
        }
        // barrier doubles as tile-reuse guard; exit when all 8 warps done
        if (__syncthreads_and(count >= KNN)) break;
    }
    __syncwarp();

    int cnt   = min(count, KNN);
    int first = (cnt > 0) ? sidx[warp][0] : 0;
    int n     = (lane < cnt) ? sidx[warp][lane] : first;

    // ---- emit: lane k owns neighbor k; warp store per channel = 128B line
    float* o1 = out1 + ((size_t)b * 67 * Mm + m) * KNN + lane;
    float* o2 = out2 + ((size_t)b * 64 * Mm + m) * KNN + lane;
    const size_t cs = (size_t)Mm * KNN;

    float4 pc = xyz[n];
    o1[0]      = __fsub_rn(pc.x, cx);
    o1[cs]     = __fsub_rn(pc.y, cy);
    o1[2 * cs] = __fsub_rn(pc.z, cz);

    const float4* row = (const float4*)g_comb + ((size_t)b * Nn + n) * 32;
    float* o1f = o1 + 3 * cs;
#pragma unroll
    for (int c4 = 0; c4 < 16; c4++) {           // feat: cols 0..63
        float4 v = row[c4];
        o1f[(4 * c4 + 0) * cs] = v.x;
        o1f[(4 * c4 + 1) * cs] = v.y;
        o1f[(4 * c4 + 2) * cs] = v.z;
        o1f[(4 * c4 + 3) * cs] = v.w;
    }
#pragma unroll
    for (int c4 = 0; c4 < 16; c4++) {           // temb: cols 64..127
        float4 w = row[16 + c4];
        o2[(4 * c4 + 0) * cs] = w.x;
        o2[(4 * c4 + 1) * cs] = w.y;
        o2[(4 * c4 + 2) * cs] = w.z;
        o2[(4 * c4 + 3) * cs] = w.w;
    }
}

// ---------------------------------------------------------------------------
extern "C" void kernel_launch(void* const* d_in, const int* in_sizes, int n_in,
                              void* d_out, int out_size)
{
    const float* pts  = (const float*)d_in[0];   // points_coords  [B,3,N]
    const float* ctr  = (const float*)d_in[1];   // centers_coords [B,3,M]
    const float* temb = (const float*)d_in[2];   // temb           [B,CT,N]
    const float* feat = (const float*)d_in[3];   // points_features[B,C,N]

    float* out1 = (float*)d_out;                                   // [B,67,M,K]
    float* out2 = out1 + (size_t)Bb * (3 + Cc) * Mm * KNN;         // [B,64,M,K]

    dim3 tb(8, 32);
    dim3 tg(Nn / 32, Cc / 32, Bb * 2);
    transpose_kernel<<<tg, tb>>>(feat, temb);

    xyz_kernel<<<(Bb * Nn) / 256, 256>>>(pts);

    fused_kernel<<<(Bb * Mm) / 8, 256>>>(ctr, out1, out2);
}

// round 6
// speedup vs baseline: 1.8698x; 1.2202x over previous
#include <cuda_runtime.h>

#define Bb   8
#define Nn   8192
#define Mm   2048
#define Cc   64
#define CTt  64
#define KNN  32
#define TILE 1024
#define PITCH 133   // odd float pitch -> conflict-free column reads

// Scratch (__device__ globals; cudaMalloc is forbidden)
// g_comb row n: [feat c0..63 | temb c0..63]  -> one 512B contiguous gather run
__device__ float  g_comb[(size_t)Bb * Nn * 128];   // 32 MB
__device__ float4 g_xyz[(size_t)Bb * Nn];          //  4 MB  (x,y,z,|p|^2)

// ---------------------------------------------------------------------------
// Prep A: transpose [B][C][N] -> combined [B][N][128]
// ---------------------------------------------------------------------------
__global__ void transpose_kernel(const float* __restrict__ feat,
                                 const float* __restrict__ temb)
{
    __shared__ float tile[32][33];
    int zz    = blockIdx.z;
    int b     = zz >> 1;
    int which = zz & 1;
    const float* src = which ? temb : feat;
    int cbase        = which ? 64 : 0;

    int n0 = blockIdx.x * 32;
    int c0 = blockIdx.y * 32;
    int j  = threadIdx.x;                     // 0..7
    int i  = threadIdx.y;                     // 0..31

    const float* s = src + (size_t)b * Cc * Nn;
    float*       d = g_comb + (size_t)b * Nn * 128;

    float4 v = *(const float4*)(s + (size_t)(c0 + i) * Nn + n0 + 4 * j);
    tile[i][4 * j + 0] = v.x;
    tile[i][4 * j + 1] = v.y;
    tile[i][4 * j + 2] = v.z;
    tile[i][4 * j + 3] = v.w;
    __syncthreads();

    float4 w;
    w.x = tile[4 * j + 0][i];
    w.y = tile[4 * j + 1][i];
    w.z = tile[4 * j + 2][i];
    w.w = tile[4 * j + 3][i];
    *(float4*)(d + (size_t)(n0 + i) * 128 + cbase + c0 + 4 * j) = w;
}

// ---------------------------------------------------------------------------
// Prep B: pack coords + squared norm (exact mul-then-add order).
// ---------------------------------------------------------------------------
__global__ void xyz_kernel(const float* __restrict__ pts)   // [B][3][N]
{
    int g = blockIdx.x * blockDim.x + threadIdx.x;
    int b = g >> 13;
    int n = g & (Nn - 1);
    const float* p = pts + (size_t)b * 3 * Nn;
    float x = p[n], y = p[Nn + n], z = p[2 * Nn + n];
    float pn = __fadd_rn(__fadd_rn(__fmul_rn(x, x), __fmul_rn(y, y)),
                         __fmul_rn(z, z));
    g_xyz[g] = make_float4(x, y, z, pn);
}

// ---------------------------------------------------------------------------
// Fused ball-query + gather + emit.  8 warps/CTA, one center per warp.
// Scan: shared 1024-point tile.  Emit: per-center smem staging so every
// gather LDG.128 touches only 4 lines (warp-per-row) and every output STG
// is one full 128B line (warp-per-channel).
// Staging layout: channel c of neighbor k at stg[k*PITCH + (c&3)*32 + (c>>2)]
//   write (lane l, comp j): addr = r*PITCH + j*32 + l  -> consecutive, CF
//   read  (chan c, k=lane): addr = l*PITCH + const     -> odd stride,  CF
// ---------------------------------------------------------------------------
__global__ void __launch_bounds__(256)
fused_kernel(const float* __restrict__ ctr,    // [B][3][M]
             float* __restrict__ out1,         // [B][67][M][K]
             float* __restrict__ out2)         // [B][64][M][K]
{
    __shared__ __align__(16) float sraw[KNN * PITCH];  // 17KB, dual-use
    __shared__ int    sidx[8][KNN];
    __shared__ float4 spc[KNN];
    __shared__ float  scen[8][3];

    float4* spts = (float4*)sraw;   // scan phase view  (TILE float4 = 16KB)
    float*  stg  = sraw;            // emit phase view  [KNN][PITCH] swizzled

    int t    = threadIdx.x;
    int warp = t >> 5;
    int lane = t & 31;
    int gw   = blockIdx.x * 8 + warp;
    int b    = gw >> 11;
    int m    = gw & (Mm - 1);

    float cx = ctr[(size_t)b * 3 * Mm + m];
    float cy = ctr[(size_t)b * 3 * Mm + Mm + m];
    float cz = ctr[(size_t)b * 3 * Mm + 2 * Mm + m];
    float cn = __fadd_rn(__fadd_rn(__fmul_rn(cx, cx), __fmul_rn(cy, cy)),
                         __fmul_rn(cz, cz));
    if (lane == 0) {
        scen[warp][0] = cx; scen[warp][1] = cy; scen[warp][2] = cz;
    }

    const float4* xyz = g_xyz + (size_t)b * Nn;
    const float R2 = (float)(0.2 * 0.2);

    // ---- ordered first-K scan over shared tiles ----
    int count = 0;
    for (int t0 = 0; t0 < Nn; t0 += TILE) {
#pragma unroll
        for (int q = 0; q < 4; q++)
            spts[t + q * 256] = xyz[t0 + t + q * 256];
        __syncthreads();

        if (count < KNN) {
            for (int g = 0; g < TILE && count < KNN; g += 128) {
                float4 p0 = spts[g + lane];
                float4 p1 = spts[g + 32 + lane];
                float4 p2 = spts[g + 64 + lane];
                float4 p3 = spts[g + 96 + lane];
#pragma unroll
                for (int i = 0; i < 4; i++) {
                    float4 p = (i == 0) ? p0 : (i == 1) ? p1
                             : (i == 2) ? p2 : p3;
                    float cross = fmaf(cz, p.z,
                                       fmaf(cy, p.y, __fmul_rn(cx, p.x)));
                    float d2 = __fsub_rn(__fadd_rn(cn, p.w),
                                         __fmul_rn(2.0f, cross));
                    bool valid = d2 < R2;
                    unsigned mask = __ballot_sync(0xffffffffu, valid);
                    if (valid) {
                        int pos = count + __popc(mask & ((1u << lane) - 1u));
                        if (pos < KNN)
                            sidx[warp][pos] = t0 + g + i * 32 + lane;
                    }
                    count += __popc(mask);
                }
            }
        }
        if (__syncthreads_and(count >= KNN)) break;
    }
    __syncwarp();

    // finalize index list (fill tail with first valid / 0)
    int cnt   = min(count, KNN);
    int first = (cnt > 0) ? sidx[warp][0] : 0;
    int n     = (lane < cnt) ? sidx[warp][lane] : first;
    __syncwarp();
    sidx[warp][lane] = n;
    __syncthreads();   // scan done; sraw is reusable, sidx complete

    // ---- emit: one center at a time, CTA-cooperative ----
    const size_t cs = (size_t)Mm * KNN;
    for (int i = 0; i < 8; i++) {
        int gwi = blockIdx.x * 8 + i;
        int bi  = gwi >> 11;
        int mi  = gwi & (Mm - 1);

        // stage 32 neighbor rows: warp w loads rows w, w+8, w+16, w+24
        const float4* combB = (const float4*)g_comb + (size_t)bi * Nn * 32;
#pragma unroll
        for (int q = 0; q < 4; q++) {
            int r  = warp + q * 8;
            int nk = sidx[i][r];
            float4 v = combB[(size_t)nk * 32 + lane];
            float* rowp = &stg[r * PITCH];
            rowp[0 * 32 + lane] = v.x;     // channel 4*lane+0
            rowp[1 * 32 + lane] = v.y;     // channel 4*lane+1
            rowp[2 * 32 + lane] = v.z;     // channel 4*lane+2
            rowp[3 * 32 + lane] = v.w;     // channel 4*lane+3
        }
        if (t < KNN)
            spc[t] = g_xyz[(size_t)bi * Nn + sidx[i][t]];
        __syncthreads();

        float* o1 = out1 + ((size_t)bi * 67 * Mm + mi) * KNN;
        float* o2 = out2 + ((size_t)bi * 64 * Mm + mi) * KNN;

        // 131 channels, warp per channel line (128B coalesced store)
#pragma unroll 4
        for (int c = warp; c < 131; c += 8) {
            float v;
            if (c < 3) {
                float4 pv = spc[lane];
                float comp = (c == 0) ? pv.x : (c == 1) ? pv.y : pv.z;
                v = __fsub_rn(comp, scen[i][c]);
            } else {
                int cc = c - 3;
                v = stg[lane * PITCH + ((cc & 3) << 5) + (cc >> 2)];
            }
            if (c < 67) o1[(size_t)c * cs + lane] = v;
            else        o2[(size_t)(c - 67) * cs + lane] = v;
        }
        __syncthreads();   // protect stg before next center overwrites
    }
}

// ---------------------------------------------------------------------------
extern "C" void kernel_launch(void* const* d_in, const int* in_sizes, int n_in,
                              void* d_out, int out_size)
{
    const float* pts  = (const float*)d_in[0];   // points_coords  [B,3,N]
    const float* ctr  = (const float*)d_in[1];   // centers_coords [B,3,M]
    const float* temb = (const float*)d_in[2];   // temb           [B,CT,N]
    const float* feat = (const float*)d_in[3];   // points_features[B,C,N]

    float* out1 = (float*)d_out;                                   // [B,67,M,K]
    float* out2 = out1 + (size_t)Bb * (3 + Cc) * Mm * KNN;         // [B,64,M,K]

    dim3 tb(8, 32);
    dim3 tg(Nn / 32, Cc / 32, Bb * 2);
    transpose_kernel<<<tg, tb>>>(feat, temb);

    xyz_kernel<<<(Bb * Nn) / 256, 256>>>(pts);

    fused_kernel<<<(Bb * Mm) / 8, 256>>>(ctr, out1, out2);
}

// round 7
// speedup vs baseline: 1.9734x; 1.0554x over previous
#include <cuda_runtime.h>

#define Bb   8
#define Nn   8192
#define Mm   2048
#define Cc   64
#define CTt  64
#define KNN  32
#define TILE 1024
#define PITCH 133   // odd float pitch -> conflict-free column reads

// Scratch (__device__ globals; cudaMalloc is forbidden)
// g_comb row n: [feat c0..63 | temb c0..63]  -> one 512B contiguous gather run
__device__ float  g_comb[(size_t)Bb * Nn * 128];   // 32 MB (L2-resident)
__device__ float4 g_xyz[(size_t)Bb * Nn];          //  4 MB  (x,y,z,|p|^2)

// ---------------------------------------------------------------------------
// Prep: transpose [B][C][N] -> combined [B][N][128], plus xyz packing.
// Input reads are single-use -> __ldcs (evict-first, don't pollute L2).
// g_comb/g_xyz writes keep default policy (must stay L2-resident for fused).
// block (8,32); grid (Nn/32, Cc/32, B*2)
// ---------------------------------------------------------------------------
__global__ void prep_kernel(const float* __restrict__ feat,
                            const float* __restrict__ temb,
                            const float* __restrict__ pts)
{
    __shared__ float tile[32][33];
    int zz    = blockIdx.z;
    int b     = zz >> 1;
    int which = zz & 1;
    const float* src = which ? temb : feat;
    int cbase        = which ? 64 : 0;

    int n0 = blockIdx.x * 32;
    int c0 = blockIdx.y * 32;
    int j  = threadIdx.x;                     // 0..7
    int i  = threadIdx.y;                     // 0..31
    int t  = i * 8 + j;                       // 0..255

    const float* s = src + (size_t)b * Cc * Nn;
    float*       d = g_comb + (size_t)b * Nn * 128;

    float4 v = __ldcs((const float4*)(s + (size_t)(c0 + i) * Nn + n0 + 4 * j));
    tile[i][4 * j + 0] = v.x;
    tile[i][4 * j + 1] = v.y;
    tile[i][4 * j + 2] = v.z;
    tile[i][4 * j + 3] = v.w;

    // xyz packing piggybacks on one block family (which==0, c0==0)
    if (which == 0 && blockIdx.y == 0 && t < 32) {
        int n = n0 + t;
        const float* p = pts + (size_t)b * 3 * Nn;
        float x = p[n], y = p[Nn + n], z = p[2 * Nn + n];
        float pn = __fadd_rn(__fadd_rn(__fmul_rn(x, x), __fmul_rn(y, y)),
                             __fmul_rn(z, z));
        g_xyz[(size_t)b * Nn + n] = make_float4(x, y, z, pn);
    }
    __syncthreads();

    float4 w;
    w.x = tile[4 * j + 0][i];
    w.y = tile[4 * j + 1][i];
    w.z = tile[4 * j + 2][i];
    w.w = tile[4 * j + 3][i];
    *(float4*)(d + (size_t)(n0 + i) * 128 + cbase + c0 + 4 * j) = w;
}

// ---------------------------------------------------------------------------
// Fused ball-query + gather + emit.  8 warps/CTA, one center per warp.
// Scan from a shared 1024-point tile; emit per-center with smem staging
// (gather LDG.128 touches 4 lines; output STG is a full 128B line).
// Output stores use __stcs so the 275MB write stream doesn't evict g_comb.
// ---------------------------------------------------------------------------
__global__ void __launch_bounds__(256)
fused_kernel(const float* __restrict__ ctr,    // [B][3][M]
             float* __restrict__ out1,         // [B][67][M][K]
             float* __restrict__ out2)         // [B][64][M][K]
{
    __shared__ __align__(16) float sraw[KNN * PITCH];  // 17KB, dual-use
    __shared__ int    sidx[8][KNN];
    __shared__ float4 spc[KNN];
    __shared__ float  scen[8][3];

    float4* spts = (float4*)sraw;   // scan phase view  (TILE float4 = 16KB)
    float*  stg  = sraw;            // emit phase view  [KNN][PITCH] swizzled

    int t    = threadIdx.x;
    int warp = t >> 5;
    int lane = t & 31;
    int gw   = blockIdx.x * 8 + warp;
    int b    = gw >> 11;
    int m    = gw & (Mm - 1);

    float cx = ctr[(size_t)b * 3 * Mm + m];
    float cy = ctr[(size_t)b * 3 * Mm + Mm + m];
    float cz = ctr[(size_t)b * 3 * Mm + 2 * Mm + m];
    float cn = __fadd_rn(__fadd_rn(__fmul_rn(cx, cx), __fmul_rn(cy, cy)),
                         __fmul_rn(cz, cz));
    if (lane == 0) {
        scen[warp][0] = cx; scen[warp][1] = cy; scen[warp][2] = cz;
    }

    const float4* xyz = g_xyz + (size_t)b * Nn;
    const float R2 = (float)(0.2 * 0.2);

    // ---- ordered first-K scan over shared tiles ----
    int count = 0;
    for (int t0 = 0; t0 < Nn; t0 += TILE) {
#pragma unroll
        for (int q = 0; q < 4; q++)
            spts[t + q * 256] = xyz[t0 + t + q * 256];
        __syncthreads();

        if (count < KNN) {
            for (int g = 0; g < TILE && count < KNN; g += 128) {
                float4 p0 = spts[g + lane];
                float4 p1 = spts[g + 32 + lane];
                float4 p2 = spts[g + 64 + lane];
                float4 p3 = spts[g + 96 + lane];
#pragma unroll
                for (int i = 0; i < 4; i++) {
                    float4 p = (i == 0) ? p0 : (i == 1) ? p1
                             : (i == 2) ? p2 : p3;
                    float cross = fmaf(cz, p.z,
                                       fmaf(cy, p.y, __fmul_rn(cx, p.x)));
                    float d2 = __fsub_rn(__fadd_rn(cn, p.w),
                                         __fmul_rn(2.0f, cross));
                    bool valid = d2 < R2;
                    unsigned mask = __ballot_sync(0xffffffffu, valid);
                    if (valid) {
                        int pos = count + __popc(mask & ((1u << lane) - 1u));
                        if (pos < KNN)
                            sidx[warp][pos] = t0 + g + i * 32 + lane;
                    }
                    count += __popc(mask);
                }
            }
        }
        if (__syncthreads_and(count >= KNN)) break;
    }
    __syncwarp();

    // finalize index list (fill tail with first valid / 0)
    int cnt   = min(count, KNN);
    int first = (cnt > 0) ? sidx[warp][0] : 0;
    int n     = (lane < cnt) ? sidx[warp][lane] : first;
    __syncwarp();
    sidx[warp][lane] = n;
    __syncthreads();   // scan done; sraw is reusable, sidx complete

    // ---- emit: one center at a time, CTA-cooperative ----
    const size_t cs = (size_t)Mm * KNN;
    for (int i = 0; i < 8; i++) {
        int gwi = blockIdx.x * 8 + i;
        int bi  = gwi >> 11;
        int mi  = gwi & (Mm - 1);

        // stage 32 neighbor rows: warp w loads rows w, w+8, w+16, w+24
        const float4* combB = (const float4*)g_comb + (size_t)bi * Nn * 32;
#pragma unroll
        for (int q = 0; q < 4; q++) {
            int r  = warp + q * 8;
            int nk = sidx[i][r];
            float4 v = combB[(size_t)nk * 32 + lane];
            float* rowp = &stg[r * PITCH];
            rowp[0 * 32 + lane] = v.x;     // channel 4*lane+0
            rowp[1 * 32 + lane] = v.y;     // channel 4*lane+1
            rowp[2 * 32 + lane] = v.z;     // channel 4*lane+2
            rowp[3 * 32 + lane] = v.w;     // channel 4*lane+3
        }
        if (t < KNN)
            spc[t] = g_xyz[(size_t)bi * Nn + sidx[i][t]];
        __syncthreads();

        float* o1 = out1 + ((size_t)bi * 67 * Mm + mi) * KNN;
        float* o2 = out2 + ((size_t)bi * 64 * Mm + mi) * KNN;

        // 131 channels, warp per channel line; streaming stores (evict-first)
#pragma unroll 4
        for (int c = warp; c < 131; c += 8) {
            float v;
            if (c < 3) {
                float4 pv = spc[lane];
                float comp = (c == 0) ? pv.x : (c == 1) ? pv.y : pv.z;
                v = __fsub_rn(comp, scen[i][c]);
            } else {
                int cc = c - 3;
                v = stg[lane * PITCH + ((cc & 3) << 5) + (cc >> 2)];
            }
            if (c < 67) __stcs(&o1[(size_t)c * cs + lane], v);
            else        __stcs(&o2[(size_t)(c - 67) * cs + lane], v);
        }
        __syncthreads();   // protect stg before next center overwrites
    }
}

// ---------------------------------------------------------------------------
extern "C" void kernel_launch(void* const* d_in, const int* in_sizes, int n_in,
                              void* d_out, int out_size)
{
    const float* pts  = (const float*)d_in[0];   // points_coords  [B,3,N]
    const float* ctr  = (const float*)d_in[1];   // centers_coords [B,3,M]
    const float* temb = (const float*)d_in[2];   // temb           [B,CT,N]
    const float* feat = (const float*)d_in[3];   // points_features[B,C,N]

    float* out1 = (float*)d_out;                                   // [B,67,M,K]
    float* out2 = out1 + (size_t)Bb * (3 + Cc) * Mm * KNN;         // [B,64,M,K]

    dim3 tb(8, 32);
    dim3 tg(Nn / 32, Cc / 32, Bb * 2);
    prep_kernel<<<tg, tb>>>(feat, temb, pts);

    fused_kernel<<<(Bb * Mm) / 8, 256>>>(ctr, out1, out2);
}